// round 17
// baseline (speedup 1.0000x reference)
#include <cuda_runtime.h>
#include <cuda_fp16.h>
#include <cstdint>

#define D_IN   128
#define D_OUT  128
#define NBASES 4
#define NCOLS  512
#define N_MAX  100096          // multiple of 256
#define NBLK   (N_MAX / 256)   // 391
#define E_MAX  655360
#define RB     296             // region width (blocks) for grid-stride regions

// ---------------- scratch ----------------
__device__ __align__(16) __half g_XWh[(size_t)N_MAX * NCOLS];  // [node][512] fp16
__device__ __align__(16) __half g_Xh[(size_t)N_MAX * D_IN];    // fp16 X
#define BT_STRIDE 136
__device__ __align__(16) __half g_Bt[NBASES][128 * BT_STRIDE];
// hist[N_MAX] | scan aggregates[NBLK]  (zeroed by one memset)
__device__ int    g_hist[N_MAX + NBLK];
__device__ int    g_rowptr[N_MAX + 1];
__device__ int    g_cursor[N_MAX];
__device__ int    g_dst_s[E_MAX];
__device__ float4 g_c_s[E_MAX];

// ---------------- helpers ----------------
static __device__ __forceinline__ uint32_t smem_u32(const void* p) {
    uint32_t a;
    asm("{ .reg .u64 t; cvta.to.shared.u64 t, %1; cvt.u32.u64 %0, t; }" : "=r"(a) : "l"(p));
    return a;
}
#define LDSM4(r, addr) \
    asm volatile("ldmatrix.sync.aligned.m8n8.x4.shared.b16 {%0,%1,%2,%3}, [%4];" \
        : "=r"((r)[0]), "=r"((r)[1]), "=r"((r)[2]), "=r"((r)[3]) : "r"(addr))
#define MMA_F16(c, a, b0, b1) \
    asm volatile("mma.sync.aligned.m16n8k16.row.col.f32.f16.f16.f32 " \
        "{%0,%1,%2,%3}, {%4,%5,%6,%7}, {%8,%9}, {%0,%1,%2,%3};" \
        : "+f"((c)[0]), "+f"((c)[1]), "+f"((c)[2]), "+f"((c)[3]) \
        : "r"((a)[0]), "r"((a)[1]), "r"((a)[2]), "r"((a)[3]), "r"(b0), "r"(b1))

static __device__ __forceinline__ uint32_t packh(__half a, __half b) {
    return ((uint32_t)__half_as_ushort(b) << 16) | (uint32_t)__half_as_ushort(a);
}

// ========== Chain A kernel 1: convert_x | prep_b ===========================
__global__ void __launch_bounds__(256)
conv_kernel(const float* __restrict__ X, const float* __restrict__ w_bases, int total4)
{
    if (blockIdx.x < RB) {
        const int i0 = blockIdx.x * 256 + threadIdx.x;
        for (int i = i0; i < total4; i += RB * 256) {
            float4 v = reinterpret_cast<const float4*>(X)[i];
            reinterpret_cast<uint2*>(g_Xh)[i] =
                make_uint2(packh(__float2half_rn(v.x), __float2half_rn(v.y)),
                           packh(__float2half_rn(v.z), __float2half_rn(v.w)));
        }
    } else {
        const int id0 = (blockIdx.x - RB) * 256 + threadIdx.x;
        for (int id = id0; id < NBASES * D_IN * D_OUT; id += 32 * 256) {
            const int nn = id & 127, k = (id >> 7) & 127, b = id >> 14;
            g_Bt[b][nn * BT_STRIDE + k] = __float2half_rn(w_bases[id]);
        }
    }
}

// ========== Chain B kernel 1: zero-out | hist ==============================
__global__ void __launch_bounds__(256)
prep_hist_kernel(const int* __restrict__ esrc, float4* __restrict__ out,
                 int out4, int E)
{
    if (blockIdx.x < RB) {
        const float4 z = make_float4(0.f, 0.f, 0.f, 0.f);
        for (int i = blockIdx.x * 256 + threadIdx.x; i < out4; i += RB * 256) out[i] = z;
    } else {
        for (int e = (blockIdx.x - RB) * 256 + threadIdx.x; e < E; e += RB * 256)
            atomicAdd(&g_hist[esrc[e]], 1);
    }
}

// ================= K_scan: single-pass scan with aggregate lookback =========
__global__ void __launch_bounds__(256)
scan_kernel(int E)
{
    __shared__ int s_w[8];
    __shared__ int s_off;
    const int t = threadIdx.x, w = t >> 5, lane = t & 31;
    const int blk = blockIdx.x;
    const int i = blk * 256 + t;

    const int x = g_hist[i];
    int v = x;
    #pragma unroll
    for (int o = 1; o < 32; o <<= 1) {
        int y = __shfl_up_sync(0xFFFFFFFF, v, o);
        if (lane >= o) v += y;
    }
    if (lane == 31) s_w[w] = v;
    __syncthreads();
    if (t < 8) {
        int sv = s_w[t];
        #pragma unroll
        for (int o = 1; o < 8; o <<= 1) {
            int y = __shfl_up_sync(0xFF, sv, o);
            if (t >= o) sv += y;
        }
        s_w[t] = sv;
    }
    __syncthreads();
    const int local_excl = ((w > 0) ? s_w[w - 1] : 0) + v - x;

    if (t == 0) {
        int total = s_w[7];
        asm volatile("st.global.release.gpu.b32 [%0], %1;"
                     :: "l"(&g_hist[N_MAX + blk]), "r"(total + 1) : "memory");
    }
    if (w == 0) {
        int sum = 0;
        for (int j0 = 0; j0 < blk; j0 += 32) {
            const int j = j0 + lane;
            int a = 0;
            if (j < blk) {
                do {
                    asm volatile("ld.global.acquire.gpu.b32 %0, [%1];"
                                 : "=r"(a) : "l"(&g_hist[N_MAX + j]) : "memory");
                } while (a == 0);
                a -= 1;
            }
            #pragma unroll
            for (int o = 16; o > 0; o >>= 1) a += __shfl_down_sync(0xFFFFFFFF, a, o);
            if (lane == 0) sum += a;
        }
        if (lane == 0) s_off = sum;
    }
    __syncthreads();

    const int r = s_off + local_excl;
    g_rowptr[i] = r;
    g_cursor[i] = r;
    if (i == N_MAX - 1) g_rowptr[N_MAX] = E;
}

// ================= perm: scatter edges into src-sorted order ================
__global__ void __launch_bounds__(256)
perm_kernel(const int* __restrict__ esrc, const int* __restrict__ edst,
            const int* __restrict__ erel, const float* __restrict__ eval,
            const float* __restrict__ w_rel, int E)
{
    const int e = blockIdx.x * 256 + threadIdx.x;
    if (e >= E) return;
    const int s = esrc[e];
    const int pos = atomicAdd(&g_cursor[s], 1);
    g_dst_s[pos] = edst[e];
    const int r = erel[e];
    const float v = eval[e];
    float4 c;
    c.x = v * __ldg(w_rel + r * NBASES + 0);
    c.y = v * __ldg(w_rel + r * NBASES + 1);
    c.z = v * __ldg(w_rel + r * NBASES + 2);
    c.w = v * __ldg(w_rel + r * NBASES + 3);
    g_c_s[pos] = c;
}

// ====== GEMM: fp16 mma.sync, 128x64 tiles, 4 CTAs/SM (round-13 exact) ======
#define AS_STRIDE 272
#define SM_A    0
#define SM_B    34816
#define SM_TOTAL (34816 + 17408)           // 52224

__global__ void __launch_bounds__(256, 4)
gemm_mma_kernel(int n_rows)
{
    extern __shared__ char smem[];
    const uint32_t sb = smem_u32(smem);
    const int tid = threadIdx.x, wid = tid >> 5, lane = tid & 31;
    const int nc = blockIdx.x;             // n-chunk 0..7
    const int base = nc >> 1, half = nc & 1;
    const int m0 = blockIdx.y * 128;

    for (int i = tid; i < 2048; i += 256) {
        const int row = i >> 4, seg = (i & 15) * 16;
        const size_t gsrc = (size_t)(m0 + row) * 256 + seg;
        uint4 hv = *reinterpret_cast<const uint4*>(reinterpret_cast<const char*>(g_Xh) + gsrc);
        *reinterpret_cast<uint4*>(smem + SM_A + row * AS_STRIDE + seg) = hv;
    }
    {
        const uint4* src = reinterpret_cast<const uint4*>(g_Bt[base] + half * 64 * BT_STRIDE);
        uint4* dst = reinterpret_cast<uint4*>(smem + SM_B);
        for (int i = tid; i < 1088; i += 256) dst[i] = src[i];
    }
    __syncthreads();

    const int warp_m = (wid & 3) * 32;
    const int warp_n = (wid >> 2) * 32;

    float acc[2][4][4];
    #pragma unroll
    for (int mt = 0; mt < 2; ++mt)
        #pragma unroll
        for (int nt = 0; nt < 4; ++nt)
            #pragma unroll
            for (int i = 0; i < 4; ++i) acc[mt][nt][i] = 0.f;

    const uint32_t a_off = (uint32_t)(warp_m + (lane & 15)) * AS_STRIDE + (lane >> 4) * 16;
    const uint32_t b_off = (uint32_t)(warp_n + ((lane >> 4) << 3) + (lane & 7)) * AS_STRIDE
                         + ((lane >> 3) & 1) * 16;

    #pragma unroll
    for (int ks = 0; ks < 8; ++ks) {
        const uint32_t kb = (uint32_t)ks * 32;
        uint32_t ah[2][4];
        LDSM4(ah[0], sb + SM_A + a_off + kb);
        LDSM4(ah[1], sb + SM_A + a_off + 16 * AS_STRIDE + kb);
        #pragma unroll
        for (int j = 0; j < 2; ++j) {
            uint32_t b[4];
            LDSM4(b, sb + SM_B + b_off + (uint32_t)j * 16 * AS_STRIDE + kb);
            #pragma unroll
            for (int mt = 0; mt < 2; ++mt) {
                MMA_F16(acc[mt][2 * j + 0], ah[mt], b[0], b[1]);
                MMA_F16(acc[mt][2 * j + 1], ah[mt], b[2], b[3]);
            }
        }
    }

    const int r_base = m0 + warp_m + (lane >> 2);
    #pragma unroll
    for (int mt = 0; mt < 2; ++mt) {
        const int row0 = r_base + mt * 16;
        #pragma unroll
        for (int nt = 0; nt < 4; ++nt) {
            const int col = nc * 64 + warp_n + nt * 8 + (lane & 3) * 2;
            *reinterpret_cast<__half2*>(g_XWh + (size_t)row0 * NCOLS + col) =
                __floats2half2_rn(acc[mt][nt][0], acc[mt][nt][1]);
            *reinterpret_cast<__half2*>(g_XWh + (size_t)(row0 + 8) * NCOLS + col) =
                __floats2half2_rn(acc[mt][nt][2], acc[mt][nt][3]);
        }
    }
}

// ================= scatter: warp-per-src ===================================
__global__ void __launch_bounds__(256)
scatter_kernel(float* __restrict__ out)
{
    const int src  = (blockIdx.x * 256 + threadIdx.x) >> 5;
    const int lane = threadIdx.x & 31;
    if (src >= N_MAX) return;
    const int beg = __ldg(g_rowptr + src);
    const int end = __ldg(g_rowptr + src + 1);
    if (beg >= end) return;

    const uint2* p = reinterpret_cast<const uint2*>(g_XWh + (size_t)src * NCOLS) + lane;
    float a[NBASES][4];
    #pragma unroll
    for (int b = 0; b < NBASES; ++b) {
        const uint2 v = __ldg(p + b * 32);
        const float2 lo = __half22float2(*reinterpret_cast<const __half2*>(&v.x));
        const float2 hi = __half22float2(*reinterpret_cast<const __half2*>(&v.y));
        a[b][0] = lo.x; a[b][1] = lo.y; a[b][2] = hi.x; a[b][3] = hi.y;
    }

    for (int j = beg; j < end; ++j) {
        const float4 c = __ldg(g_c_s + j);
        const int d = __ldg(g_dst_s + j);
        float4 acc;
        acc.x = fmaf(c.x, a[0][0], fmaf(c.y, a[1][0], fmaf(c.z, a[2][0], c.w * a[3][0])));
        acc.y = fmaf(c.x, a[0][1], fmaf(c.y, a[1][1], fmaf(c.z, a[2][1], c.w * a[3][1])));
        acc.z = fmaf(c.x, a[0][2], fmaf(c.y, a[1][2], fmaf(c.z, a[2][2], c.w * a[3][2])));
        acc.w = fmaf(c.x, a[0][3], fmaf(c.y, a[1][3], fmaf(c.z, a[2][3], c.w * a[3][3])));
        float* q = out + (size_t)d * D_OUT + lane * 4;
        asm volatile("red.global.add.v4.f32 [%0], {%1, %2, %3, %4};"
                     :: "l"(q), "f"(acc.x), "f"(acc.y), "f"(acc.z), "f"(acc.w)
                     : "memory");
    }
}

// ================= launch: fork-join, serial fallback ======================
extern "C" void kernel_launch(void* const* d_in, const int* in_sizes, int n_in,
                              void* d_out, int out_size)
{
    const float* X       = (const float*)d_in[0];
    const int*   esrc    = (const int*)  d_in[1];
    const int*   edst    = (const int*)  d_in[2];
    const int*   erel    = (const int*)  d_in[3];
    const float* eval    = (const float*)d_in[4];
    const float* w_bases = (const float*)d_in[5];
    const float* w_rel   = (const float*)d_in[6];
    float*       out     = (float*)d_out;

    const int n = in_sizes[0] / D_IN;   // 100000
    const int E = in_sizes[1];          // 640000

    // one-time init (runs on the uncaptured correctness call)
    static bool init_done = false;
    static bool fork_ok = false;
    static cudaStream_t s1 = nullptr;
    static cudaEvent_t evFork = nullptr, evJoin = nullptr;
    static void* hist_ptr = nullptr;
    if (!init_done) {
        init_done = true;
        cudaFuncSetAttribute(gemm_mma_kernel,
                             cudaFuncAttributeMaxDynamicSharedMemorySize, SM_TOTAL);
        cudaGetSymbolAddress(&hist_ptr, g_hist);
        fork_ok =
            (cudaStreamCreateWithFlags(&s1, cudaStreamNonBlocking) == cudaSuccess) &&
            (cudaEventCreateWithFlags(&evFork, cudaEventDisableTiming) == cudaSuccess) &&
            (cudaEventCreateWithFlags(&evJoin, cudaEventDisableTiming) == cudaSuccess);
    }

    const int total4 = n * D_IN / 4;
    const int out4 = out_size / 4;
    const dim3 g1(8, (n + 127) / 128);

    if (fork_ok) {
        // ---- fork: chain A on s1 ----
        cudaEventRecord(evFork, 0);
        cudaStreamWaitEvent(s1, evFork, 0);
        conv_kernel<<<RB + 32, 256, 0, s1>>>(X, w_bases, total4);
        gemm_mma_kernel<<<g1, 256, SM_TOTAL, s1>>>(n);
        cudaEventRecord(evJoin, s1);

        // ---- chain B on the captured stream ----
        cudaMemsetAsync(hist_ptr, 0, (size_t)(N_MAX + NBLK) * sizeof(int));
        prep_hist_kernel<<<2 * RB, 256>>>(esrc, (float4*)d_out, out4, E);
        scan_kernel<<<NBLK, 256>>>(E);
        perm_kernel<<<(E + 255) / 256, 256>>>(esrc, edst, erel, eval, w_rel, E);

        // ---- join, then scatter ----
        cudaStreamWaitEvent(0, evJoin, 0);
        scatter_kernel<<<N_MAX / 8, 256>>>(out);
    } else {
        // serial fallback (round-13 topology)
        cudaMemsetAsync(hist_ptr, 0, (size_t)(N_MAX + NBLK) * sizeof(int));
        conv_kernel<<<RB + 32, 256>>>(X, w_bases, total4);
        prep_hist_kernel<<<2 * RB, 256>>>(esrc, (float4*)d_out, out4, E);
        scan_kernel<<<NBLK, 256>>>(E);
        perm_kernel<<<(E + 255) / 256, 256>>>(esrc, edst, erel, eval, w_rel, E);
        gemm_mma_kernel<<<g1, 256, SM_TOTAL>>>(n);
        scatter_kernel<<<N_MAX / 8, 256>>>(out);
    }
}